// round 8
// baseline (speedup 1.0000x reference)
#include <cuda_runtime.h>
#include <cstdint>

#define BB 16384
#define TT 2048

// Scratch: x transposed to [T, B]; padded by one timestep so the prefetch of
// t+1 never branches (last prefetched value is read but never used).
__device__ float g_xT[(size_t)BB * (size_t)(TT + 1)];

typedef unsigned long long ull;

__device__ __forceinline__ ull pk2(float a, float b) {
    ull r; asm("mov.b64 %0, {%1, %2};" : "=l"(r) : "f"(a), "f"(b)); return r;
}
__device__ __forceinline__ void upk2(ull v, float& a, float& b) {
    asm("mov.b64 {%0, %1}, %2;" : "=f"(a), "=f"(b) : "l"(v));
}
__device__ __forceinline__ ull ffma2(ull a, ull b, ull c) {
    ull d; asm("fma.rn.f32x2 %0, %1, %2, %3;" : "=l"(d) : "l"(a), "l"(b), "l"(c)); return d;
}
// MUFU.TANH — single-instruction tanh (sm_75+)
__device__ __forceinline__ float tanh_mufu(float x) {
    float y; asm("tanh.approx.f32 %0, %1;" : "=f"(y) : "f"(x)); return y;
}
// sigmoid with the 0.5 input scale PRE-FOLDED into weights/biases:
// caller passes a = 0.5*(gi+gh); sigmoid = 0.5*tanh(a) + 0.5
__device__ __forceinline__ float sig_from_half(float a) {
    return fmaf(0.5f, tanh_mufu(a), 0.5f);
}

// ---------------------------------------------------------------------------
// Kernel 1: transpose x [B, T] -> g_xT [T, B]
// ---------------------------------------------------------------------------
__global__ void transpose_kernel(const float* __restrict__ x) {
    __shared__ float tile[32][33];
    int t0 = blockIdx.x * 32;
    int b0 = blockIdx.y * 32;
    int tx = threadIdx.x, ty = threadIdx.y;
#pragma unroll
    for (int i = 0; i < 4; i++) {
        tile[ty + i * 8][tx] = x[(size_t)(b0 + ty + i * 8) * TT + (t0 + tx)];
    }
    __syncthreads();
#pragma unroll
    for (int i = 0; i < 4; i++) {
        g_xT[(size_t)(t0 + ty + i * 8) * BB + (b0 + tx)] = tile[tx][ty + i * 8];
    }
}

// ---------------------------------------------------------------------------
// Kernel 2: GRU scan, 16-way hidden split, k-packed f32x2 dots, 4 elems/group,
//           ONE WAVE (2048 warps; 1024 blocks x 64 thr, 7 blocks/SM).
// Round-8 refinements over round 7:
//   - two swapped SMEM pointers, constant offsets -> zero address ALU in loop
//   - packed bias constants as the addend of the FIRST ffma2 of each chain
//     (no accumulator-init packs); x*w_ih folded into the scalar tail FMA
//   - chunk-grouped SMEM loads so ptxas pipelines loads ahead of the FMAs
// ---------------------------------------------------------------------------

#define NE 4      // batch elements per 16-lane group
#define SLOT 20   // floats per element h slot (16 + 4 pad)
#define GRPS 4    // 16-lane groups per 64-thread block

__global__ __launch_bounds__(64, 7)
void gru_kernel(const float* __restrict__ w_ih, const float* __restrict__ w_hh,
                const float* __restrict__ b_ih, const float* __restrict__ b_hh,
                const float* __restrict__ w_fc, const float* __restrict__ b_fc,
                float* __restrict__ out)
{
    __shared__ float hbuf[2][GRPS][NE][SLOT];

    int tid = threadIdx.x;
    int j   = tid & 15;                       // owned hidden index
    int grp = tid >> 4;                       // group within block (0..3)
    int gid = (blockIdx.x * 64 + tid) >> 4;   // global group; elements 4gid..4gid+3

    // --- k-packed register weights: 8 ull per gate row ---
    ull wr2[8], wz2[8], wn2[8];
#pragma unroll
    for (int m = 0; m < 8; m++) {
        wr2[m] = pk2(0.5f * __ldg(&w_hh[j * 16 + 2 * m]),
                     0.5f * __ldg(&w_hh[j * 16 + 2 * m + 1]));
        wz2[m] = pk2(0.5f * __ldg(&w_hh[(16 + j) * 16 + 2 * m]),
                     0.5f * __ldg(&w_hh[(16 + j) * 16 + 2 * m + 1]));
        wn2[m] = pk2(__ldg(&w_hh[(32 + j) * 16 + 2 * m]),
                     __ldg(&w_hh[(32 + j) * 16 + 2 * m + 1]));
    }

    // --- scalar gate-input constants ---
    float wirf = 0.5f * __ldg(&w_ih[j]);
    float wizf = 0.5f * __ldg(&w_ih[16 + j]);
    float winf = __ldg(&w_ih[32 + j]);
    float bsrf = 0.5f * (__ldg(&b_ih[j]) + __ldg(&b_hh[j]));
    float bszf = 0.5f * (__ldg(&b_ih[16 + j]) + __ldg(&b_hh[16 + j]));
    float binf = __ldg(&b_ih[32 + j]);
    float bhnf = __ldg(&b_hh[32 + j]);
    // packed bias constants (bias in lo half; hi half 0) used as the addend of
    // the first ffma2 of each accumulation chain
    ull bR0 = pk2(bsrf, 0.0f);
    ull bZ0 = pk2(bszf, 0.0f);
    ull bN0 = pk2(bhnf, 0.0f);

    float hown[NE];
    float* wrp = &hbuf[0][grp][0][0];         // write target this step
    float* rdp = &hbuf[1][grp][0][0];         // read source this step
#pragma unroll
    for (int e = 0; e < NE; e++) {
        hown[e] = 0.0f;
        rdp[e * SLOT + j] = 0.0f;             // zero initial h in first read buf
    }
    __syncwarp();

    const float4* xp = ((const float4*)g_xT) + gid;
    float4 xv = __ldg(xp);
    xp += (BB / 4);

    for (int t = 0; t < TT; t++) {
        float4 xnext = __ldg(xp);             // padded array: always valid
        xp += (BB / 4);
        float xe[NE] = {xv.x, xv.y, xv.z, xv.w};

        ull aR[NE], aZ[NE], aN[NE];

        // ---- chunk 0: loads + chain-init FMAs (bias consts as addend) ----
        {
            ulonglong2 v0 = *(const ulonglong2*)(rdp + 0 * SLOT);
            ulonglong2 v1 = *(const ulonglong2*)(rdp + 1 * SLOT);
            ulonglong2 v2 = *(const ulonglong2*)(rdp + 2 * SLOT);
            ulonglong2 v3 = *(const ulonglong2*)(rdp + 3 * SLOT);
            aR[0] = ffma2(wr2[0], v0.x, bR0); aR[0] = ffma2(wr2[1], v0.y, aR[0]);
            aR[1] = ffma2(wr2[0], v1.x, bR0); aR[1] = ffma2(wr2[1], v1.y, aR[1]);
            aR[2] = ffma2(wr2[0], v2.x, bR0); aR[2] = ffma2(wr2[1], v2.y, aR[2]);
            aR[3] = ffma2(wr2[0], v3.x, bR0); aR[3] = ffma2(wr2[1], v3.y, aR[3]);
            aZ[0] = ffma2(wz2[0], v0.x, bZ0); aZ[0] = ffma2(wz2[1], v0.y, aZ[0]);
            aZ[1] = ffma2(wz2[0], v1.x, bZ0); aZ[1] = ffma2(wz2[1], v1.y, aZ[1]);
            aZ[2] = ffma2(wz2[0], v2.x, bZ0); aZ[2] = ffma2(wz2[1], v2.y, aZ[2]);
            aZ[3] = ffma2(wz2[0], v3.x, bZ0); aZ[3] = ffma2(wz2[1], v3.y, aZ[3]);
            aN[0] = ffma2(wn2[0], v0.x, bN0); aN[0] = ffma2(wn2[1], v0.y, aN[0]);
            aN[1] = ffma2(wn2[0], v1.x, bN0); aN[1] = ffma2(wn2[1], v1.y, aN[1]);
            aN[2] = ffma2(wn2[0], v2.x, bN0); aN[2] = ffma2(wn2[1], v2.y, aN[2]);
            aN[3] = ffma2(wn2[0], v3.x, bN0); aN[3] = ffma2(wn2[1], v3.y, aN[3]);
        }
        // ---- chunks 1..3 ----
#pragma unroll
        for (int c = 1; c < 4; c++) {
            ulonglong2 v0 = *(const ulonglong2*)(rdp + 0 * SLOT + 4 * c);
            ulonglong2 v1 = *(const ulonglong2*)(rdp + 1 * SLOT + 4 * c);
            ulonglong2 v2 = *(const ulonglong2*)(rdp + 2 * SLOT + 4 * c);
            ulonglong2 v3 = *(const ulonglong2*)(rdp + 3 * SLOT + 4 * c);
            aR[0] = ffma2(wr2[2 * c], v0.x, aR[0]); aR[0] = ffma2(wr2[2 * c + 1], v0.y, aR[0]);
            aR[1] = ffma2(wr2[2 * c], v1.x, aR[1]); aR[1] = ffma2(wr2[2 * c + 1], v1.y, aR[1]);
            aR[2] = ffma2(wr2[2 * c], v2.x, aR[2]); aR[2] = ffma2(wr2[2 * c + 1], v2.y, aR[2]);
            aR[3] = ffma2(wr2[2 * c], v3.x, aR[3]); aR[3] = ffma2(wr2[2 * c + 1], v3.y, aR[3]);
            aZ[0] = ffma2(wz2[2 * c], v0.x, aZ[0]); aZ[0] = ffma2(wz2[2 * c + 1], v0.y, aZ[0]);
            aZ[1] = ffma2(wz2[2 * c], v1.x, aZ[1]); aZ[1] = ffma2(wz2[2 * c + 1], v1.y, aZ[1]);
            aZ[2] = ffma2(wz2[2 * c], v2.x, aZ[2]); aZ[2] = ffma2(wz2[2 * c + 1], v2.y, aZ[2]);
            aZ[3] = ffma2(wz2[2 * c], v3.x, aZ[3]); aZ[3] = ffma2(wz2[2 * c + 1], v3.y, aZ[3]);
            aN[0] = ffma2(wn2[2 * c], v0.x, aN[0]); aN[0] = ffma2(wn2[2 * c + 1], v0.y, aN[0]);
            aN[1] = ffma2(wn2[2 * c], v1.x, aN[1]); aN[1] = ffma2(wn2[2 * c + 1], v1.y, aN[1]);
            aN[2] = ffma2(wn2[2 * c], v2.x, aN[2]); aN[2] = ffma2(wn2[2 * c + 1], v2.y, aN[2]);
            aN[3] = ffma2(wn2[2 * c], v3.x, aN[3]); aN[3] = ffma2(wn2[2 * c + 1], v3.y, aN[3]);
        }

        // ---- tails: 4 independent scalar chains; x*w_ih folded here ----
#pragma unroll
        for (int e = 0; e < NE; e++) {
            float lo, hi;
            upk2(aR[e], lo, hi);
            float r = sig_from_half(fmaf(xe[e], wirf, lo + hi));
            upk2(aZ[e], lo, hi);
            float z = sig_from_half(fmaf(xe[e], wizf, lo + hi));
            upk2(aN[e], lo, hi);
            float gh = lo + hi;
            float gi = fmaf(xe[e], winf, binf);
            float n  = tanh_mufu(fmaf(r, gh, gi));
            float h  = fmaf(z, hown[e] - n, n);   // (1-z)n + z h
            hown[e] = h;
            wrp[e * SLOT + j] = h;
        }
        __syncwarp();
        float* tmp = rdp; rdp = wrp; wrp = tmp;   // swap buffers

        xv = xnext;
    }

    // FC epilogue: out[b] = sum_j h[b][j] * w_fc[j] + b_fc  (reduce over 16 lanes)
    float wf = __ldg(&w_fc[j]);
    float s[NE];
#pragma unroll
    for (int e = 0; e < NE; e++) s[e] = hown[e] * wf;
#pragma unroll
    for (int d = 1; d < 16; d <<= 1) {
#pragma unroll
        for (int e = 0; e < NE; e++) {
            s[e] += __shfl_xor_sync(0xffffffffu, s[e], d);
        }
    }
    if (j == 0) {
        float bf = __ldg(b_fc);
        float4 o;
        o.x = s[0] + bf;
        o.y = s[1] + bf;
        o.z = s[2] + bf;
        o.w = s[3] + bf;
        *(float4*)(out + 4 * gid) = o;
    }
}

// ---------------------------------------------------------------------------
extern "C" void kernel_launch(void* const* d_in, const int* in_sizes, int n_in,
                              void* d_out, int out_size)
{
    const float* x    = (const float*)d_in[0];
    const float* w_ih = (const float*)d_in[1];
    const float* w_hh = (const float*)d_in[2];
    const float* b_ih = (const float*)d_in[3];
    const float* b_hh = (const float*)d_in[4];
    const float* w_fc = (const float*)d_in[5];
    const float* b_fc = (const float*)d_in[6];
    float* out = (float*)d_out;

    dim3 tb(32, 8);
    dim3 tg(TT / 32, BB / 32);
    transpose_kernel<<<tg, tb>>>(x);

    // 16384 elems / 4 per 16-lane group * 16 lanes = 65536 threads
    // = 1024 blocks x 64 threads = 2048 warps -> ONE wave at 7 blocks/SM.
    gru_kernel<<<1024, 64>>>(w_ih, w_hh, b_ih, b_hh, w_fc, b_fc, out);
}

// round 9
// speedup vs baseline: 1.0794x; 1.0794x over previous
#include <cuda_runtime.h>
#include <cstdint>

#define BB 16384
#define TT 2048

// Scratch: x transposed to [T, B]; padded by one timestep so the prefetch of
// t+1 never branches (last prefetched value is read but never used).
__device__ float g_xT[(size_t)BB * (size_t)(TT + 1)];

typedef unsigned long long ull;

__device__ __forceinline__ ull pk2(float a, float b) {
    ull r; asm("mov.b64 %0, {%1, %2};" : "=l"(r) : "f"(a), "f"(b)); return r;
}
__device__ __forceinline__ void upk2(ull v, float& a, float& b) {
    asm("mov.b64 {%0, %1}, %2;" : "=f"(a), "=f"(b) : "l"(v));
}
__device__ __forceinline__ ull ffma2(ull a, ull b, ull c) {
    ull d; asm("fma.rn.f32x2 %0, %1, %2, %3;" : "=l"(d) : "l"(a), "l"(b), "l"(c)); return d;
}
// MUFU.TANH — single-instruction tanh (sm_75+)
__device__ __forceinline__ float tanh_mufu(float x) {
    float y; asm("tanh.approx.f32 %0, %1;" : "=f"(y) : "f"(x)); return y;
}
// sigmoid with the 0.5 input scale PRE-FOLDED into weights/biases:
// caller passes a = 0.5*(gi+gh); sigmoid = 0.5*tanh(a) + 0.5
__device__ __forceinline__ float sig_from_half(float a) {
    return fmaf(0.5f, tanh_mufu(a), 0.5f);
}

// ---------------------------------------------------------------------------
// Kernel 1: transpose x [B, T] -> g_xT [T, B]
// ---------------------------------------------------------------------------
__global__ void transpose_kernel(const float* __restrict__ x) {
    __shared__ float tile[32][33];
    int t0 = blockIdx.x * 32;
    int b0 = blockIdx.y * 32;
    int tx = threadIdx.x, ty = threadIdx.y;
#pragma unroll
    for (int i = 0; i < 4; i++) {
        tile[ty + i * 8][tx] = x[(size_t)(b0 + ty + i * 8) * TT + (t0 + tx)];
    }
    __syncthreads();
#pragma unroll
    for (int i = 0; i < 4; i++) {
        g_xT[(size_t)(t0 + ty + i * 8) * BB + (b0 + tx)] = tile[tx][ty + i * 8];
    }
}

// ---------------------------------------------------------------------------
// Kernel 2: GRU scan — round-6 structure (best known), re-shaped for waves.
//   - 16-lane group handles one packed batch pair (f32x2 over 2 elements).
//   - Lane j owns hidden index j and gate rows {j, 16+j, 32+j}; 48 f32x2
//     weights live in registers (96 regs).
//   - 64-thread blocks, __launch_bounds__(64, 9): reg cap 112 ≈ true need,
//     9 blocks/SM -> 1332 concurrent blocks -> 2048 blocks = 1.54 waves
//     (round 6 was 1.73 waves at 128-thread granularity).
//   - Per-step h exchange via ping-pong SMEM with STATIC swapped pointers
//     (no dynamic buffer index -> no per-step address ALU).
//   - r/z weights+biases pre-scaled by 0.5 (sigmoid via tanh identity).
// ---------------------------------------------------------------------------

#define QPAD 20   // ull per pair slot (16 + 4 pad -> 8-bank offset between slots)

__global__ __launch_bounds__(64, 9)
void gru_kernel(const float* __restrict__ w_ih, const float* __restrict__ w_hh,
                const float* __restrict__ b_ih, const float* __restrict__ b_hh,
                const float* __restrict__ w_fc, const float* __restrict__ b_fc,
                float* __restrict__ out)
{
    __shared__ ull hbuf[2][4][QPAD];

    int tid = threadIdx.x;
    int g   = blockIdx.x * 64 + tid;
    int j   = g & 15;          // owned hidden index
    int p   = g >> 4;          // global batch-pair index (elements 2p, 2p+1)
    int pb  = tid >> 4;        // pair slot within block (0..3)

    // --- register-resident recurrent weights (duplicated f32x2) ---
    ull wr_[16], wz_[16], wn_[16];
#pragma unroll
    for (int k = 0; k < 16; k++) {
        float a = 0.5f * __ldg(&w_hh[j * 16 + k]);          // r row, half-scaled
        float b = 0.5f * __ldg(&w_hh[(16 + j) * 16 + k]);   // z row, half-scaled
        float c = __ldg(&w_hh[(32 + j) * 16 + k]);          // n row
        wr_[k] = pk2(a, a);
        wz_[k] = pk2(b, b);
        wn_[k] = pk2(c, c);
    }

    // --- gate-input constants ---
    float wirf = 0.5f * __ldg(&w_ih[j]);
    float wizf = 0.5f * __ldg(&w_ih[16 + j]);
    float winf = __ldg(&w_ih[32 + j]);
    float bsrf = 0.5f * (__ldg(&b_ih[j]) + __ldg(&b_hh[j]));
    float bszf = 0.5f * (__ldg(&b_ih[16 + j]) + __ldg(&b_hh[16 + j]));
    float binf = __ldg(&b_ih[32 + j]);
    float bhnf = __ldg(&b_hh[32 + j]);
    ull wirp = pk2(wirf, wirf), wizp = pk2(wizf, wizf), winp = pk2(winf, winf);
    ull bsrp = pk2(bsrf, bsrf), bszp = pk2(bszf, bszf);
    ull binp = pk2(binf, binf), bhnp = pk2(bhnf, bhnf);

    // hx[k] = packed h_k for both elements; hown = own h_j
    ull hx[16];
#pragma unroll
    for (int k = 0; k < 16; k++) hx[k] = 0ull;
    ull hown = 0ull;

    // ping-pong pointers, static offsets
    ull* wrp = &hbuf[0][pb][0];
    ull* rdp = &hbuf[1][pb][0];

    const float2* xp = ((const float2*)g_xT) + p;
    float2 xv = __ldg(xp);
    xp += (BB / 2);

    for (int t = 0; t < TT; t++) {
        ull x2 = pk2(xv.x, xv.y);
        float2 xnext = __ldg(xp);      // padded array: always valid
        xp += (BB / 2);

        // three gate pre-activations (independent FMA chains)
        ull aR = ffma2(x2, wirp, bsrp);
        ull aZ = ffma2(x2, wizp, bszp);
        ull aN = bhnp;
#pragma unroll
        for (int k = 0; k < 16; k++) {
            aR = ffma2(wr_[k], hx[k], aR);
            aZ = ffma2(wz_[k], hx[k], aZ);
            aN = ffma2(wn_[k], hx[k], aN);
        }

        float a0, a1;
        upk2(aR, a0, a1);
        ull rr = pk2(sig_from_half(a0), sig_from_half(a1));
        float z0, z1;
        upk2(aZ, z0, z1);
        z0 = sig_from_half(z0);
        z1 = sig_from_half(z1);

        ull gi  = ffma2(x2, winp, binp);
        ull pre = ffma2(rr, aN, gi);
        float p0, p1;
        upk2(pre, p0, p1);
        float n0 = tanh_mufu(p0);
        float n1 = tanh_mufu(p1);

        float h0, h1;
        upk2(hown, h0, h1);
        h0 = fmaf(z0, h0 - n0, n0);    // (1-z)n + z h
        h1 = fmaf(z1, h1 - n1, n1);
        hown = pk2(h0, h1);

        // exchange: write own h, sync, reload all 16
        wrp[j] = hown;
        __syncwarp();
#pragma unroll
        for (int k2 = 0; k2 < 8; k2++) {
            ulonglong2 v = *(const ulonglong2*)(wrp + 2 * k2);
            hx[2 * k2]     = v.x;
            hx[2 * k2 + 1] = v.y;
        }
        ull* tmp = rdp; rdp = wrp; wrp = tmp;

        xv = xnext;
    }

    // FC epilogue: out[b] = sum_j h[b][j] * w_fc[j] + b_fc
    float wf = __ldg(&w_fc[j]);
    float h0, h1;
    upk2(hown, h0, h1);
    float s0 = h0 * wf;
    float s1 = h1 * wf;
#pragma unroll
    for (int d = 1; d < 16; d <<= 1) {
        s0 += __shfl_xor_sync(0xffffffffu, s0, d);
        s1 += __shfl_xor_sync(0xffffffffu, s1, d);
    }
    if (j == 0) {
        float bf = __ldg(b_fc);
        float2 o;
        o.x = s0 + bf;
        o.y = s1 + bf;
        *(float2*)(out + 2 * p) = o;
    }
}

// ---------------------------------------------------------------------------
extern "C" void kernel_launch(void* const* d_in, const int* in_sizes, int n_in,
                              void* d_out, int out_size)
{
    const float* x    = (const float*)d_in[0];
    const float* w_ih = (const float*)d_in[1];
    const float* w_hh = (const float*)d_in[2];
    const float* b_ih = (const float*)d_in[3];
    const float* b_hh = (const float*)d_in[4];
    const float* w_fc = (const float*)d_in[5];
    const float* b_fc = (const float*)d_in[6];
    float* out = (float*)d_out;

    dim3 tb(32, 8);
    dim3 tg(TT / 32, BB / 32);
    transpose_kernel<<<tg, tb>>>(x);

    // 16384 batch / 2 per 16-lane group * 16 lanes = 131072 threads
    // = 2048 blocks x 64 threads; 9 blocks/SM -> 1.54 waves.
    gru_kernel<<<2048, 64>>>(w_ih, w_hh, b_ih, b_hh, w_fc, b_fc, out);
}

// round 10
// speedup vs baseline: 1.2540x; 1.1618x over previous
#include <cuda_runtime.h>
#include <cstdint>

#define BB 16384
#define TT 2048

// Scratch: x transposed to [T, B]; padded by one timestep so the prefetch of
// t+1 never branches (last prefetched value is read but never used).
__device__ float g_xT[(size_t)BB * (size_t)(TT + 1)];

typedef unsigned long long ull;

__device__ __forceinline__ ull pk2(float a, float b) {
    ull r; asm("mov.b64 %0, {%1, %2};" : "=l"(r) : "f"(a), "f"(b)); return r;
}
__device__ __forceinline__ void upk2(ull v, float& a, float& b) {
    asm("mov.b64 {%0, %1}, %2;" : "=f"(a), "=f"(b) : "l"(v));
}
__device__ __forceinline__ ull ffma2(ull a, ull b, ull c) {
    ull d; asm("fma.rn.f32x2 %0, %1, %2, %3;" : "=l"(d) : "l"(a), "l"(b), "l"(c)); return d;
}
// MUFU.TANH — single-instruction tanh (sm_75+)
__device__ __forceinline__ float tanh_mufu(float x) {
    float y; asm("tanh.approx.f32 %0, %1;" : "=f"(y) : "f"(x)); return y;
}
// sigmoid with the 0.5 input scale PRE-FOLDED into weights/biases:
// caller passes a = 0.5*(gi+gh); sigmoid = 0.5*tanh(a) + 0.5
__device__ __forceinline__ float sig_from_half(float a) {
    return fmaf(0.5f, tanh_mufu(a), 0.5f);
}
__device__ __forceinline__ float hadd2(ull v) {
    float a, b; upk2(v, a, b); return a + b;
}

// ---------------------------------------------------------------------------
// Kernel 1: transpose x [B, T] -> g_xT [T, B]
// ---------------------------------------------------------------------------
__global__ void transpose_kernel(const float* __restrict__ x) {
    __shared__ float tile[32][33];
    int t0 = blockIdx.x * 32;
    int b0 = blockIdx.y * 32;
    int tx = threadIdx.x, ty = threadIdx.y;
#pragma unroll
    for (int i = 0; i < 4; i++) {
        tile[ty + i * 8][tx] = x[(size_t)(b0 + ty + i * 8) * TT + (t0 + tx)];
    }
    __syncthreads();
#pragma unroll
    for (int i = 0; i < 4; i++) {
        g_xT[(size_t)(t0 + ty + i * 8) * BB + (b0 + tx)] = tile[tx][ty + i * 8];
    }
}

// ---------------------------------------------------------------------------
// Kernel 2: GRU scan — k-packed weights (48 regs), 2 elements/thread,
//           h streamed from SMEM with 2-chunk lookahead. NO spills by design.
//   - Lane j (= g&15) owns hidden index j, gate rows {j,16+j,32+j}.
//     Weights k-packed (w_2m, w_2m+1): 24 ull = 48 regs.
//   - 16-lane group = one batch pair; 6 independent chains (3 gates x 2 elems).
//   - SMEM exchange layout: per-group region of 48 floats (adjacent groups
//     16 banks apart within a warp), elemA at +0, elemB at +20 -> both the
//     STS.32 writes and the broadcast LDS.128 reads are conflict-free.
//   - __launch_bounds__(64,10): cap 102 regs, 20 warps/SM (5/SMSP),
//     1480 concurrent blocks -> 2048 blocks = 1.38 waves.
//   - r/z weights+biases pre-scaled by 0.5 (sigmoid via tanh identity).
// ---------------------------------------------------------------------------

#define GREG 48   // floats per group region
#define EOFF 20   // elemB offset within region

__global__ __launch_bounds__(64, 10)
void gru_kernel(const float* __restrict__ w_ih, const float* __restrict__ w_hh,
                const float* __restrict__ b_ih, const float* __restrict__ b_hh,
                const float* __restrict__ w_fc, const float* __restrict__ b_fc,
                float* __restrict__ out)
{
    __shared__ float hbuf[2][4 * GREG];

    int tid = threadIdx.x;
    int g   = blockIdx.x * 64 + tid;
    int j   = g & 15;          // owned hidden index
    int p   = g >> 4;          // global batch-pair index (elements 2p, 2p+1)
    int grp = tid >> 4;        // group within block (0..3)

    // --- k-packed register weights: 8 ull per gate row, 24 ull total ---
    ull wr2[8], wz2[8], wn2[8];
#pragma unroll
    for (int m = 0; m < 8; m++) {
        wr2[m] = pk2(0.5f * __ldg(&w_hh[j * 16 + 2 * m]),
                     0.5f * __ldg(&w_hh[j * 16 + 2 * m + 1]));
        wz2[m] = pk2(0.5f * __ldg(&w_hh[(16 + j) * 16 + 2 * m]),
                     0.5f * __ldg(&w_hh[(16 + j) * 16 + 2 * m + 1]));
        wn2[m] = pk2(__ldg(&w_hh[(32 + j) * 16 + 2 * m]),
                     __ldg(&w_hh[(32 + j) * 16 + 2 * m + 1]));
    }

    // --- scalar gate-input constants ---
    float wirf = 0.5f * __ldg(&w_ih[j]);
    float wizf = 0.5f * __ldg(&w_ih[16 + j]);
    float winf = __ldg(&w_ih[32 + j]);
    float bsrf = 0.5f * (__ldg(&b_ih[j]) + __ldg(&b_hh[j]));
    float bszf = 0.5f * (__ldg(&b_ih[16 + j]) + __ldg(&b_hh[16 + j]));
    float binf = __ldg(&b_ih[32 + j]);
    float bhnf = __ldg(&b_hh[32 + j]);
    // packed bias addends for the FIRST ffma2 of each chain (bias in lo half)
    ull bR2 = pk2(bsrf, 0.0f);
    ull bZ2 = pk2(bszf, 0.0f);
    ull bN2 = pk2(bhnf, 0.0f);

    // ping-pong read/write pointers (static offsets, swapped each step)
    float* rdA = &hbuf[0][grp * GREG];
    float* rdB = rdA + EOFF;
    float* wrA = &hbuf[1][grp * GREG];
    float* wrB = wrA + EOFF;

    float hA = 0.0f, hB = 0.0f;
    rdA[j] = 0.0f;
    rdB[j] = 0.0f;
    __syncwarp();

    const float2* xp = ((const float2*)g_xT) + p;
    float2 xv = __ldg(xp);
    xp += (BB / 2);

    for (int t = 0; t < TT; t++) {
        float xA = xv.x, xB = xv.y;
        float2 xnext = __ldg(xp);      // padded array: always valid
        xp += (BB / 2);

        // ---- dot phase: 6 chains, chunks with 1-chunk lookahead ----
        ulonglong2 a0 = *(const ulonglong2*)(rdA);
        ulonglong2 b0 = *(const ulonglong2*)(rdB);
        ulonglong2 a1 = *(const ulonglong2*)(rdA + 4);
        ulonglong2 b1 = *(const ulonglong2*)(rdB + 4);

        ull aRA = ffma2(wr2[0], a0.x, bR2);
        ull aRB = ffma2(wr2[0], b0.x, bR2);
        ull aZA = ffma2(wz2[0], a0.x, bZ2);
        ull aZB = ffma2(wz2[0], b0.x, bZ2);
        ull aNA = ffma2(wn2[0], a0.x, bN2);
        ull aNB = ffma2(wn2[0], b0.x, bN2);
        aRA = ffma2(wr2[1], a0.y, aRA);  aRB = ffma2(wr2[1], b0.y, aRB);
        aZA = ffma2(wz2[1], a0.y, aZA);  aZB = ffma2(wz2[1], b0.y, aZB);
        aNA = ffma2(wn2[1], a0.y, aNA);  aNB = ffma2(wn2[1], b0.y, aNB);

        ulonglong2 a2 = *(const ulonglong2*)(rdA + 8);
        ulonglong2 b2 = *(const ulonglong2*)(rdB + 8);
        aRA = ffma2(wr2[2], a1.x, aRA);  aRB = ffma2(wr2[2], b1.x, aRB);
        aZA = ffma2(wz2[2], a1.x, aZA);  aZB = ffma2(wz2[2], b1.x, aZB);
        aNA = ffma2(wn2[2], a1.x, aNA);  aNB = ffma2(wn2[2], b1.x, aNB);
        aRA = ffma2(wr2[3], a1.y, aRA);  aRB = ffma2(wr2[3], b1.y, aRB);
        aZA = ffma2(wz2[3], a1.y, aZA);  aZB = ffma2(wz2[3], b1.y, aZB);
        aNA = ffma2(wn2[3], a1.y, aNA);  aNB = ffma2(wn2[3], b1.y, aNB);

        ulonglong2 a3 = *(const ulonglong2*)(rdA + 12);
        ulonglong2 b3 = *(const ulonglong2*)(rdB + 12);
        aRA = ffma2(wr2[4], a2.x, aRA);  aRB = ffma2(wr2[4], b2.x, aRB);
        aZA = ffma2(wz2[4], a2.x, aZA);  aZB = ffma2(wz2[4], b2.x, aZB);
        aNA = ffma2(wn2[4], a2.x, aNA);  aNB = ffma2(wn2[4], b2.x, aNB);
        aRA = ffma2(wr2[5], a2.y, aRA);  aRB = ffma2(wr2[5], b2.y, aRB);
        aZA = ffma2(wz2[5], a2.y, aZA);  aZB = ffma2(wz2[5], b2.y, aZB);
        aNA = ffma2(wn2[5], a2.y, aNA);  aNB = ffma2(wn2[5], b2.y, aNB);

        aRA = ffma2(wr2[6], a3.x, aRA);  aRB = ffma2(wr2[6], b3.x, aRB);
        aZA = ffma2(wz2[6], a3.x, aZA);  aZB = ffma2(wz2[6], b3.x, aZB);
        aNA = ffma2(wn2[6], a3.x, aNA);  aNB = ffma2(wn2[6], b3.x, aNB);
        aRA = ffma2(wr2[7], a3.y, aRA);  aRB = ffma2(wr2[7], b3.y, aRB);
        aZA = ffma2(wz2[7], a3.y, aZA);  aZB = ffma2(wz2[7], b3.y, aZB);
        aNA = ffma2(wn2[7], a3.y, aNA);  aNB = ffma2(wn2[7], b3.y, aNB);

        // ---- tails: 2 independent scalar chains ----
        float rA = sig_from_half(fmaf(xA, wirf, hadd2(aRA)));
        float rB = sig_from_half(fmaf(xB, wirf, hadd2(aRB)));
        float zA = sig_from_half(fmaf(xA, wizf, hadd2(aZA)));
        float zB = sig_from_half(fmaf(xB, wizf, hadd2(aZB)));
        float nA = tanh_mufu(fmaf(rA, hadd2(aNA), fmaf(xA, winf, binf)));
        float nB = tanh_mufu(fmaf(rB, hadd2(aNB), fmaf(xB, winf, binf)));
        hA = fmaf(zA, hA - nA, nA);    // (1-z)n + z h
        hB = fmaf(zB, hB - nB, nB);

        // ---- exchange ----
        wrA[j] = hA;
        wrB[j] = hB;
        __syncwarp();
        float* t0p = rdA; rdA = wrA; wrA = t0p;
        float* t1p = rdB; rdB = wrB; wrB = t1p;

        xv = xnext;
    }

    // FC epilogue: out[b] = sum_j h[b][j] * w_fc[j] + b_fc
    float wf = __ldg(&w_fc[j]);
    float s0 = hA * wf;
    float s1 = hB * wf;
#pragma unroll
    for (int d = 1; d < 16; d <<= 1) {
        s0 += __shfl_xor_sync(0xffffffffu, s0, d);
        s1 += __shfl_xor_sync(0xffffffffu, s1, d);
    }
    if (j == 0) {
        float bf = __ldg(b_fc);
        float2 o;
        o.x = s0 + bf;
        o.y = s1 + bf;
        *(float2*)(out + 2 * p) = o;
    }
}

// ---------------------------------------------------------------------------
extern "C" void kernel_launch(void* const* d_in, const int* in_sizes, int n_in,
                              void* d_out, int out_size)
{
    const float* x    = (const float*)d_in[0];
    const float* w_ih = (const float*)d_in[1];
    const float* w_hh = (const float*)d_in[2];
    const float* b_ih = (const float*)d_in[3];
    const float* b_hh = (const float*)d_in[4];
    const float* w_fc = (const float*)d_in[5];
    const float* b_fc = (const float*)d_in[6];
    float* out = (float*)d_out;

    dim3 tb(32, 8);
    dim3 tg(TT / 32, BB / 32);
    transpose_kernel<<<tg, tb>>>(x);

    // 16384 batch / 2 per 16-lane group * 16 lanes = 131072 threads
    // = 2048 blocks x 64 threads; 10 blocks/SM -> 1.38 waves.
    gru_kernel<<<2048, 64>>>(w_ih, w_hh, b_ih, b_hh, w_fc, b_fc, out);
}

// round 11
// speedup vs baseline: 1.2605x; 1.0052x over previous
#include <cuda_runtime.h>
#include <cstdint>

#define BB 16384
#define TT 2048

// Scratch: x transposed to [T, B]; padded by one timestep so the prefetch of
// t+1 never branches (last prefetched value is read but never used).
__device__ float g_xT[(size_t)BB * (size_t)(TT + 1)];

typedef unsigned long long ull;

__device__ __forceinline__ ull pk2(float a, float b) {
    ull r; asm("mov.b64 %0, {%1, %2};" : "=l"(r) : "f"(a), "f"(b)); return r;
}
__device__ __forceinline__ void upk2(ull v, float& a, float& b) {
    asm("mov.b64 {%0, %1}, %2;" : "=f"(a), "=f"(b) : "l"(v));
}
__device__ __forceinline__ ull ffma2(ull a, ull b, ull c) {
    ull d; asm("fma.rn.f32x2 %0, %1, %2, %3;" : "=l"(d) : "l"(a), "l"(b), "l"(c)); return d;
}
__device__ __forceinline__ ull fsub2(ull a, ull b) {
    ull d; asm("sub.rn.f32x2 %0, %1, %2;" : "=l"(d) : "l"(a), "l"(b)); return d;
}
// MUFU.TANH — single-instruction tanh (sm_75+)
__device__ __forceinline__ float tanh_mufu(float x) {
    float y; asm("tanh.approx.f32 %0, %1;" : "=f"(y) : "f"(x)); return y;
}
__device__ __forceinline__ float hadd2(ull v) {
    float a, b; upk2(v, a, b); return a + b;
}

// ---------------------------------------------------------------------------
// Kernel 1: transpose x [B, T] -> g_xT [T, B]
// ---------------------------------------------------------------------------
__global__ void transpose_kernel(const float* __restrict__ x) {
    __shared__ float tile[32][33];
    int t0 = blockIdx.x * 32;
    int b0 = blockIdx.y * 32;
    int tx = threadIdx.x, ty = threadIdx.y;
#pragma unroll
    for (int i = 0; i < 4; i++) {
        tile[ty + i * 8][tx] = x[(size_t)(b0 + ty + i * 8) * TT + (t0 + tx)];
    }
    __syncthreads();
#pragma unroll
    for (int i = 0; i < 4; i++) {
        g_xT[(size_t)(t0 + ty + i * 8) * BB + (b0 + tx)] = tile[tx][ty + i * 8];
    }
}

// ---------------------------------------------------------------------------
// Kernel 2: GRU scan — k-packed dot (48 weight regs, spill-free) + PACKED
//           f32x2 tails (elemA, elemB packed after the horizontal adds).
//   - Lane j (= g&15) owns hidden index j, gate rows {j,16+j,32+j}.
//   - 16-lane group = one batch pair; dot = 6 packed chains (3 gates x 2).
//   - Tails: pack (A,B) -> fma.rn.f32x2 for x-terms, sigmoid scale-adds,
//     n pre-activation and h-update; only tanh stays scalar (MUFU).
//   - SMEM exchange layout identical to round 10 (conflict-free).
//   - __launch_bounds__(64,10): 20 warps/SM, 1480 concurrent blocks,
//     2048 blocks = 1.38 waves.
//   - r/z recurrent weights+biases pre-scaled by 0.5 (sigmoid via tanh).
// ---------------------------------------------------------------------------

#define GREG 48   // floats per group region
#define EOFF 20   // elemB offset within region

__global__ __launch_bounds__(64, 10)
void gru_kernel(const float* __restrict__ w_ih, const float* __restrict__ w_hh,
                const float* __restrict__ b_ih, const float* __restrict__ b_hh,
                const float* __restrict__ w_fc, const float* __restrict__ b_fc,
                float* __restrict__ out)
{
    __shared__ float hbuf[2][4 * GREG];

    int tid = threadIdx.x;
    int g   = blockIdx.x * 64 + tid;
    int j   = g & 15;          // owned hidden index
    int p   = g >> 4;          // global batch-pair index (elements 2p, 2p+1)
    int grp = tid >> 4;        // group within block (0..3)

    // --- k-packed register weights: 8 ull per gate row, 24 ull total ---
    ull wr2[8], wz2[8], wn2[8];
#pragma unroll
    for (int m = 0; m < 8; m++) {
        wr2[m] = pk2(0.5f * __ldg(&w_hh[j * 16 + 2 * m]),
                     0.5f * __ldg(&w_hh[j * 16 + 2 * m + 1]));
        wz2[m] = pk2(0.5f * __ldg(&w_hh[(16 + j) * 16 + 2 * m]),
                     0.5f * __ldg(&w_hh[(16 + j) * 16 + 2 * m + 1]));
        wn2[m] = pk2(__ldg(&w_hh[(32 + j) * 16 + 2 * m]),
                     __ldg(&w_hh[(32 + j) * 16 + 2 * m + 1]));
    }

    // --- packed tail constants ---
    float wirf = 0.5f * __ldg(&w_ih[j]);
    float wizf = 0.5f * __ldg(&w_ih[16 + j]);
    float winf = __ldg(&w_ih[32 + j]);
    float bsrf = 0.5f * (__ldg(&b_ih[j]) + __ldg(&b_hh[j]));
    float bszf = 0.5f * (__ldg(&b_ih[16 + j]) + __ldg(&b_hh[16 + j]));
    float binf = __ldg(&b_ih[32 + j]);
    float bhnf = __ldg(&b_hh[32 + j]);
    // dot-chain init addends (bias in lo half; hi half 0)
    ull bR2 = pk2(bsrf, 0.0f);
    ull bZ2 = pk2(bszf, 0.0f);
    ull bN2 = pk2(bhnf, 0.0f);
    // packed duplicated constants for the tail
    ull wirp  = pk2(wirf, wirf);
    ull wizp  = pk2(wizf, wizf);
    ull winp  = pk2(winf, winf);
    ull binp2 = pk2(binf, binf);
    ull halfp = pk2(0.5f, 0.5f);

    // ping-pong read/write pointers (static offsets, swapped each step)
    float* rdA = &hbuf[0][grp * GREG];
    float* rdB = rdA + EOFF;
    float* wrA = &hbuf[1][grp * GREG];
    float* wrB = wrA + EOFF;

    ull hpk = 0ull;             // packed (hA, hB)
    rdA[j] = 0.0f;
    rdB[j] = 0.0f;
    __syncwarp();

    const float2* xp = ((const float2*)g_xT) + p;
    float2 xv = __ldg(xp);
    xp += (BB / 2);

    for (int t = 0; t < TT; t++) {
        ull x2 = pk2(xv.x, xv.y);
        float2 xnext = __ldg(xp);      // padded array: always valid
        xp += (BB / 2);

        // ---- dot phase: 6 packed chains, 2-chunk lookahead ----
        ulonglong2 a0 = *(const ulonglong2*)(rdA);
        ulonglong2 b0 = *(const ulonglong2*)(rdB);
        ulonglong2 a1 = *(const ulonglong2*)(rdA + 4);
        ulonglong2 b1 = *(const ulonglong2*)(rdB + 4);

        ull aRA = ffma2(wr2[0], a0.x, bR2);
        ull aRB = ffma2(wr2[0], b0.x, bR2);
        ull aZA = ffma2(wz2[0], a0.x, bZ2);
        ull aZB = ffma2(wz2[0], b0.x, bZ2);
        ull aNA = ffma2(wn2[0], a0.x, bN2);
        ull aNB = ffma2(wn2[0], b0.x, bN2);
        aRA = ffma2(wr2[1], a0.y, aRA);  aRB = ffma2(wr2[1], b0.y, aRB);
        aZA = ffma2(wz2[1], a0.y, aZA);  aZB = ffma2(wz2[1], b0.y, aZB);
        aNA = ffma2(wn2[1], a0.y, aNA);  aNB = ffma2(wn2[1], b0.y, aNB);

        ulonglong2 a2 = *(const ulonglong2*)(rdA + 8);
        ulonglong2 b2 = *(const ulonglong2*)(rdB + 8);
        aRA = ffma2(wr2[2], a1.x, aRA);  aRB = ffma2(wr2[2], b1.x, aRB);
        aZA = ffma2(wz2[2], a1.x, aZA);  aZB = ffma2(wz2[2], b1.x, aZB);
        aNA = ffma2(wn2[2], a1.x, aNA);  aNB = ffma2(wn2[2], b1.x, aNB);
        aRA = ffma2(wr2[3], a1.y, aRA);  aRB = ffma2(wr2[3], b1.y, aRB);
        aZA = ffma2(wz2[3], a1.y, aZA);  aZB = ffma2(wz2[3], b1.y, aZB);
        aNA = ffma2(wn2[3], a1.y, aNA);  aNB = ffma2(wn2[3], b1.y, aNB);

        ulonglong2 a3 = *(const ulonglong2*)(rdA + 12);
        ulonglong2 b3 = *(const ulonglong2*)(rdB + 12);
        aRA = ffma2(wr2[4], a2.x, aRA);  aRB = ffma2(wr2[4], b2.x, aRB);
        aZA = ffma2(wz2[4], a2.x, aZA);  aZB = ffma2(wz2[4], b2.x, aZB);
        aNA = ffma2(wn2[4], a2.x, aNA);  aNB = ffma2(wn2[4], b2.x, aNB);
        aRA = ffma2(wr2[5], a2.y, aRA);  aRB = ffma2(wr2[5], b2.y, aRB);
        aZA = ffma2(wz2[5], a2.y, aZA);  aZB = ffma2(wz2[5], b2.y, aZB);
        aNA = ffma2(wn2[5], a2.y, aNA);  aNB = ffma2(wn2[5], b2.y, aNB);

        aRA = ffma2(wr2[6], a3.x, aRA);  aRB = ffma2(wr2[6], b3.x, aRB);
        aZA = ffma2(wz2[6], a3.x, aZA);  aZB = ffma2(wz2[6], b3.x, aZB);
        aNA = ffma2(wn2[6], a3.x, aNA);  aNB = ffma2(wn2[6], b3.x, aNB);
        aRA = ffma2(wr2[7], a3.y, aRA);  aRB = ffma2(wr2[7], b3.y, aRB);
        aZA = ffma2(wz2[7], a3.y, aZA);  aZB = ffma2(wz2[7], b3.y, aZB);
        aNA = ffma2(wn2[7], a3.y, aNA);  aNB = ffma2(wn2[7], b3.y, aNB);

        // ---- packed tail ----
        // horizontal adds, then pack (A,B)
        ull sR = pk2(hadd2(aRA), hadd2(aRB));   // 0.5*(gh_r + b) per elem
        ull sZ = pk2(hadd2(aZA), hadd2(aZB));
        ull gN = pk2(hadd2(aNA), hadd2(aNB));   // gh_n (full scale, b included)
        // add x-terms (packed)
        sR = ffma2(x2, wirp, sR);               // 0.5*(gi_r + gh_r)
        sZ = ffma2(x2, wizp, sZ);
        ull gI = ffma2(x2, winp, binp2);        // gi_n
        // sigmoids via scalar tanh + packed scale-add
        float lo, hi;
        upk2(sR, lo, hi);
        ull tR = pk2(tanh_mufu(lo), tanh_mufu(hi));
        upk2(sZ, lo, hi);
        ull tZ = pk2(tanh_mufu(lo), tanh_mufu(hi));
        ull rr = ffma2(halfp, tR, halfp);       // r = 0.5 tanh + 0.5
        ull zz = ffma2(halfp, tZ, halfp);
        // n = tanh(gi_n + r * gh_n)
        ull npre = ffma2(rr, gN, gI);
        upk2(npre, lo, hi);
        ull nn = pk2(tanh_mufu(lo), tanh_mufu(hi));
        // h' = n + z*(h - n)   (packed)
        ull dd = fsub2(hpk, nn);
        hpk = ffma2(zz, dd, nn);

        // ---- exchange ----
        float hA, hB;
        upk2(hpk, hA, hB);
        wrA[j] = hA;
        wrB[j] = hB;
        __syncwarp();
        float* t0p = rdA; rdA = wrA; wrA = t0p;
        float* t1p = rdB; rdB = wrB; wrB = t1p;

        xv = xnext;
    }

    // FC epilogue: out[b] = sum_j h[b][j] * w_fc[j] + b_fc
    float wf = __ldg(&w_fc[j]);
    float hA, hB;
    upk2(hpk, hA, hB);
    float s0 = hA * wf;
    float s1 = hB * wf;
#pragma unroll
    for (int d = 1; d < 16; d <<= 1) {
        s0 += __shfl_xor_sync(0xffffffffu, s0, d);
        s1 += __shfl_xor_sync(0xffffffffu, s1, d);
    }
    if (j == 0) {
        float bf = __ldg(b_fc);
        float2 o;
        o.x = s0 + bf;
        o.y = s1 + bf;
        *(float2*)(out + 2 * p) = o;
    }
}

// ---------------------------------------------------------------------------
extern "C" void kernel_launch(void* const* d_in, const int* in_sizes, int n_in,
                              void* d_out, int out_size)
{
    const float* x    = (const float*)d_in[0];
    const float* w_ih = (const float*)d_in[1];
    const float* w_hh = (const float*)d_in[2];
    const float* b_ih = (const float*)d_in[3];
    const float* b_hh = (const float*)d_in[4];
    const float* w_fc = (const float*)d_in[5];
    const float* b_fc = (const float*)d_in[6];
    float* out = (float*)d_out;

    dim3 tb(32, 8);
    dim3 tg(TT / 32, BB / 32);
    transpose_kernel<<<tg, tb>>>(x);

    // 16384 batch / 2 per 16-lane group * 16 lanes = 131072 threads
    // = 2048 blocks x 64 threads; 10 blocks/SM -> 1.38 waves.
    gru_kernel<<<2048, 64>>>(w_ih, w_hh, b_ih, b_hh, w_fc, b_fc, out);
}